// round 14
// baseline (speedup 1.0000x reference)
#include <cuda_runtime.h>
#include <cstdint>

// Inputs (metadata order):
//   0 origins [N,3] f32   1 directions [N,3] f32   2 center [3] f32
//   3 radius  [1]  f32    4 W1 [3,128] f32         5 b1 [128] f32
//   6 W2 [128,3] f32      7 b2 [3] f32
// Output: color [N,3] f32

#define MAX_ITERS 64
#define NPAIR 64          // 128 hidden units as 64 f32x2 pairs
#define TPB 128
#define RPT 4             // 4 CONSECUTIVE rays per thread -> float4 I/O

typedef unsigned long long ull;

// Union-based pack/unpack: ptxas aliases f32x2 halves in place (no MOVs).
static __device__ __forceinline__ ull pack2(float lo, float hi) {
    union { float2 f; ull u; } t;
    t.f = make_float2(lo, hi);
    return t.u;
}
static __device__ __forceinline__ void unpack2(ull v, float& lo, float& hi) {
    union { float2 f; ull u; } t;
    t.u = v;
    lo = t.f.x;
    hi = t.f.y;
}
// Packed dual-fp32 FMA (Blackwell f32x2 pipe; ptxas never emits this from C++)
static __device__ __forceinline__ ull ffma2(ull a, ull b, ull c) {
    ull d;
    asm("fma.rn.f32x2 %0, %1, %2, %3;" : "=l"(d) : "l"(a), "l"(b), "l"(c));
    return d;
}
// Single-MUFU sqrt (rel err ~3.4e-7)
static __device__ __forceinline__ float fsqrt_fast(float x) {
    float y;
    asm("sqrt.approx.f32 %0, %1;" : "=f"(y) : "f"(x));
    return y;
}

// 12 floats viewed as 3 float4 — vector I/O, scalar register access.
union F12 { float4 v[3]; float f[12]; };

__global__ __launch_bounds__(TPB, 8)
void sphere_trace_mlp_kernel(
    const float* __restrict__ origins,
    const float* __restrict__ dirs,
    const float* __restrict__ center,
    const float* __restrict__ radius,
    const float* __restrict__ W1,   // [3,128] row-major
    const float* __restrict__ b1,   // [128]
    const float* __restrict__ W2,   // [128,3] row-major
    const float* __restrict__ b2,   // [3]
    float* __restrict__ out,        // [N,3]
    int n)
{
    // Shared weights, pre-packed for f32x2 consumption. Pair p = units (2p, 2p+1).
    __shared__ float4 sA[NPAIR];  // {W1[0][j], W1[0][j+1], W1[1][j], W1[1][j+1]}
    __shared__ float4 sB[NPAIR];  // {W1[2][j], W1[2][j+1], b1[j],    b1[j+1]}
    __shared__ float4 sC[NPAIR];  // {W2[j][0], W2[j+1][0], W2[j][1], W2[j+1][1]}
    __shared__ float2 sD[NPAIR];  // {W2[j][2], W2[j+1][2]}

    const int tid = threadIdx.x;
    if (tid < NPAIR) {
        const int j = 2 * tid;
        sA[tid] = make_float4(W1[j],       W1[j + 1],
                              W1[128 + j], W1[128 + j + 1]);
        sB[tid] = make_float4(W1[256 + j], W1[256 + j + 1],
                              b1[j],       b1[j + 1]);
        sC[tid] = make_float4(W2[3 * j],     W2[3 * j + 3],
                              W2[3 * j + 1], W2[3 * j + 4]);
        sD[tid] = make_float2(W2[3 * j + 2], W2[3 * j + 5]);
    }

    const int ray0 = blockIdx.x * (TPB * RPT) + tid * RPT; // 4 consecutive rays
    const int n3   = 3 * n;
    const bool fullQ = (ray0 + RPT <= n);
    const int f4 = (ray0 * 3) >> 2;       // ray0 multiple of 4 -> exact

    const float cx = center[0], cy = center[1], cz = center[2];
    const float r  = radius[0];
    const float r2 = r * r;

    // ---- Vector ray load: 12 floats = 3 LDG.128 per tensor ----
    F12 uo, ud;
    if (fullQ) {
        const float4* __restrict__ O4 = (const float4*)origins;
        const float4* __restrict__ D4 = (const float4*)dirs;
        uo.v[0] = O4[f4]; uo.v[1] = O4[f4 + 1]; uo.v[2] = O4[f4 + 2];
        ud.v[0] = D4[f4]; ud.v[1] = D4[f4 + 1]; ud.v[2] = D4[f4 + 2];
    } else {  // tail thread: guarded scalar gather
        #pragma unroll
        for (int e = 0; e < 12; ++e) {
            const int f = ray0 * 3 + e;
            uo.f[e] = (f < n3) ? origins[f] : 0.0f;
            ud.f[e] = (f < n3) ? dirs[f]    : 0.0f;
        }
    }

    // ---- Ray classification (replaces the 64-iter march) ----
    // Unit d => sdf(t) = sqrt(t^2 + 2*hb*t + c0) - r, hb = (o-c).d, c0 = |o-c|^2.
    // Sphere tracing converges to t* = -hb - sqrt(disc), disc = hb^2 - c0 + r^2,
    // per-step contraction q = 1 - cos(alpha), cos(alpha) = sqrt(disc)/r.
    //  clear hit  (hb<0, disc > 0.04 r^2): ref s64 <= 0.8^63 ~ 8e-7 << eps and
    //     |t* - t64| <= 4e-6 -> identical mask & color.
    //  clear miss (hb>=0, or disc <= -2e-4): ref s64 > 1e-4 -> zeroed anyway.
    //  band (else, P ~ 4e-6/ray): exact 64-iteration reference recurrence.
    // p = o + t*d is computed HERE while o,d are live (no later reload).
    float hbv[RPT], c0v[RPT];
    float tt[RPT];
    bool  hit[RPT];
    bool  band_any = false;
    ull px2[RPT], py2[RPT], pz2[RPT];

    #pragma unroll
    for (int k = 0; k < RPT; ++k) {
        const float ox = uo.f[3 * k], oy = uo.f[3 * k + 1], oz = uo.f[3 * k + 2];
        const float dx = ud.f[3 * k], dy = ud.f[3 * k + 1], dz = ud.f[3 * k + 2];
        const float ux = ox - cx, uy = oy - cy, uz = oz - cz;
        const float c0 = fmaf(ux, ux, fmaf(uy, uy, uz * uz));
        const float hb = fmaf(ux, dx, fmaf(uy, dy, uz * dz));
        const float disc = fmaf(hb, hb, r2 - c0);
        const bool  toward = (hb < 0.0f);
        const bool  clear_hit = toward && (disc > 0.04f * r2);
        const bool  in_band = toward && !clear_hit && (disc > -2e-4f);
        band_any |= in_band;
        hit[k] = clear_hit;
        const float t = clear_hit ? (-hb - fsqrt_fast(disc)) : 0.0f;
        tt[k]  = t;
        hbv[k] = hb;
        c0v[k] = c0;
        px2[k] = pack2(fmaf(t, dx, ox), fmaf(t, dx, ox));
        py2[k] = pack2(fmaf(t, dy, oy), fmaf(t, dy, oy));
        pz2[k] = pack2(fmaf(t, dz, oz), fmaf(t, dz, oz));
    }

    if (__any_sync(0xffffffffu, band_any)) {
        // Rare path (~5e-4 of warps): exact reference loop; o,d still live.
        #pragma unroll
        for (int k = 0; k < RPT; ++k) {
            const float b = 2.0f * hbv[k];
            float t = 0.0f, s = 0.0f;
            #pragma unroll 1
            for (int it = 0; it < MAX_ITERS; ++it) {
                s = sqrtf(fmaf(t, t + b, c0v[k])) - r;
                t += s;
            }
            hit[k] = (s < 1e-4f);
            const float px = fmaf(t, ud.f[3 * k],     uo.f[3 * k]);
            const float py = fmaf(t, ud.f[3 * k + 1], uo.f[3 * k + 1]);
            const float pz = fmaf(t, ud.f[3 * k + 2], uo.f[3 * k + 2]);
            px2[k] = pack2(px, px);
            py2[k] = pack2(py, py);
            pz2[k] = pack2(pz, pz);
        }
    }

    __syncthreads();   // shared weights ready

    // ---- MLP: h = relu(p@W1 + b1); col = sigmoid(h@W2 + b2) ----
    // Per pair: 4 broadcast LDS feed 24 FFMA2 (fma pipe) + 8 FMNMX (alu pipe).
    ull a0[RPT], a1[RPT], a2[RPT];
    #pragma unroll
    for (int k = 0; k < RPT; ++k) { a0[k] = 0ull; a1[k] = 0ull; a2[k] = 0ull; }

    const ulonglong2* __restrict__ Au = (const ulonglong2*)sA;
    const ulonglong2* __restrict__ Bu = (const ulonglong2*)sB;
    const ulonglong2* __restrict__ Cu = (const ulonglong2*)sC;
    const ull*        __restrict__ Du = (const ull*)sD;

    // Double-buffered weight loads: pair p+1's LDS issue before pair p's math.
    ulonglong2 wa = Au[0], wb = Bu[0], wc = Cu[0];
    ull        wd = Du[0];

    #pragma unroll 8
    for (int p = 0; p < NPAIR; ++p) {
        const int q = (p + 1) & (NPAIR - 1);
        const ulonglong2 na = Au[q];
        const ulonglong2 nb = Bu[q];
        const ulonglong2 nc = Cu[q];
        const ull        nd = Du[q];

        #pragma unroll
        for (int k = 0; k < RPT; ++k) {
            ull h = wb.y;
            h = ffma2(px2[k], wa.x, h);
            h = ffma2(py2[k], wa.y, h);
            h = ffma2(pz2[k], wb.x, h);
            float hl, hh;
            unpack2(h, hl, hh);
            hl = fmaxf(hl, 0.0f);      // relu on the alu pipe (in-place)
            hh = fmaxf(hh, 0.0f);
            h = pack2(hl, hh);
            a0[k] = ffma2(h, wc.x, a0[k]);
            a1[k] = ffma2(h, wc.y, a1[k]);
            a2[k] = ffma2(h, wd,   a2[k]);
        }

        wa = na; wb = nb; wc = nc; wd = nd;
    }

    // ---- Epilogue: sigmoid + vector store ----
    const float bb0 = b2[0], bb1 = b2[1], bb2 = b2[2];
    F12 uc;
    #pragma unroll
    for (int k = 0; k < RPT; ++k) {
        float l0, h0, l1, h1, l2, h2;
        unpack2(a0[k], l0, h0);
        unpack2(a1[k], l1, h1);
        unpack2(a2[k], l2, h2);
        const float z0 = bb0 + l0 + h0;
        const float z1 = bb1 + l1 + h1;
        const float z2 = bb2 + l2 + h2;
        const float c0 = __fdividef(1.0f, 1.0f + __expf(-z0));
        const float c1 = __fdividef(1.0f, 1.0f + __expf(-z1));
        const float c2 = __fdividef(1.0f, 1.0f + __expf(-z2));
        uc.f[3 * k]     = hit[k] ? c0 : 0.0f;
        uc.f[3 * k + 1] = hit[k] ? c1 : 0.0f;
        uc.f[3 * k + 2] = hit[k] ? c2 : 0.0f;
    }

    if (fullQ) {
        float4* __restrict__ OUT4 = (float4*)out;
        OUT4[f4]     = uc.v[0];
        OUT4[f4 + 1] = uc.v[1];
        OUT4[f4 + 2] = uc.v[2];
    } else {
        #pragma unroll
        for (int e = 0; e < 12; ++e) {
            const int f = ray0 * 3 + e;
            if (f < n3) out[f] = uc.f[e];
        }
    }
}

extern "C" void kernel_launch(void* const* d_in, const int* in_sizes, int n_in,
                              void* d_out, int out_size) {
    const float* origins = (const float*)d_in[0];
    const float* dirs    = (const float*)d_in[1];
    const float* center  = (const float*)d_in[2];
    const float* radius  = (const float*)d_in[3];
    const float* W1      = (const float*)d_in[4];
    const float* b1      = (const float*)d_in[5];
    const float* W2      = (const float*)d_in[6];
    const float* b2      = (const float*)d_in[7];
    float* out = (float*)d_out;

    const int n = in_sizes[0] / 3;
    const int per_block = TPB * RPT;
    const int blocks = (n + per_block - 1) / per_block;
    sphere_trace_mlp_kernel<<<blocks, TPB>>>(origins, dirs, center, radius,
                                             W1, b1, W2, b2, out, n);
}

// round 15
// speedup vs baseline: 1.0477x; 1.0477x over previous
#include <cuda_runtime.h>
#include <cstdint>

// Inputs (metadata order):
//   0 origins [N,3] f32   1 directions [N,3] f32   2 center [3] f32
//   3 radius  [1]  f32    4 W1 [3,128] f32         5 b1 [128] f32
//   6 W2 [128,3] f32      7 b2 [3] f32
// Output: color [N,3] f32

#define MAX_ITERS 64
#define NPAIR 64          // 128 hidden units as 64 f32x2 pairs
#define TPB 128
#define RPT 4             // 4 CONSECUTIVE rays per thread -> float4 I/O

typedef unsigned long long ull;

// Union-based pack/unpack: ptxas aliases f32x2 halves in place (no MOVs).
static __device__ __forceinline__ ull pack2(float lo, float hi) {
    union { float2 f; ull u; } t;
    t.f = make_float2(lo, hi);
    return t.u;
}
static __device__ __forceinline__ void unpack2(ull v, float& lo, float& hi) {
    union { float2 f; ull u; } t;
    t.u = v;
    lo = t.f.x;
    hi = t.f.y;
}
// Packed dual-fp32 FMA (Blackwell f32x2 pipe; ptxas never emits this from C++)
static __device__ __forceinline__ ull ffma2(ull a, ull b, ull c) {
    ull d;
    asm("fma.rn.f32x2 %0, %1, %2, %3;" : "=l"(d) : "l"(a), "l"(b), "l"(c));
    return d;
}
// Single-MUFU sqrt (rel err ~3.4e-7)
static __device__ __forceinline__ float fsqrt_fast(float x) {
    float y;
    asm("sqrt.approx.f32 %0, %1;" : "=f"(y) : "f"(x));
    return y;
}

// 12 floats viewed as 3 float4 — vector I/O, scalar register access.
union F12 { float4 v[3]; float f[12]; };

// (128, 6): ~84-reg budget. The 64-reg cap at (128,8) forced ptxas to recycle
// registers across the 4 ray chains + weight double-buffer, serializing the
// MLP (R8/R13/R14 all pinned at regs=64, issue ~53%). Trade occupancy we
// proved we don't need (R9) for scheduling freedom we do.
__global__ __launch_bounds__(TPB, 6)
void sphere_trace_mlp_kernel(
    const float* __restrict__ origins,
    const float* __restrict__ dirs,
    const float* __restrict__ center,
    const float* __restrict__ radius,
    const float* __restrict__ W1,   // [3,128] row-major
    const float* __restrict__ b1,   // [128]
    const float* __restrict__ W2,   // [128,3] row-major
    const float* __restrict__ b2,   // [3]
    float* __restrict__ out,        // [N,3]
    int n)
{
    // Shared weights, pre-packed for f32x2 consumption. Pair p = units (2p, 2p+1).
    __shared__ float4 sA[NPAIR];  // {W1[0][j], W1[0][j+1], W1[1][j], W1[1][j+1]}
    __shared__ float4 sB[NPAIR];  // {W1[2][j], W1[2][j+1], b1[j],    b1[j+1]}
    __shared__ float4 sC[NPAIR];  // {W2[j][0], W2[j+1][0], W2[j][1], W2[j+1][1]}
    __shared__ float2 sD[NPAIR];  // {W2[j][2], W2[j+1][2]}

    const int tid = threadIdx.x;
    if (tid < NPAIR) {
        const int j = 2 * tid;
        sA[tid] = make_float4(W1[j],       W1[j + 1],
                              W1[128 + j], W1[128 + j + 1]);
        sB[tid] = make_float4(W1[256 + j], W1[256 + j + 1],
                              b1[j],       b1[j + 1]);
        sC[tid] = make_float4(W2[3 * j],     W2[3 * j + 3],
                              W2[3 * j + 1], W2[3 * j + 4]);
        sD[tid] = make_float2(W2[3 * j + 2], W2[3 * j + 5]);
    }

    const int ray0 = blockIdx.x * (TPB * RPT) + tid * RPT; // 4 consecutive rays
    const int n3   = 3 * n;
    const bool fullQ = (ray0 + RPT <= n);
    const int f4 = (ray0 * 3) >> 2;       // ray0 multiple of 4 -> exact

    const float cx = center[0], cy = center[1], cz = center[2];
    const float r  = radius[0];
    const float r2 = r * r;

    // ---- Vector ray load: 12 floats = 3 LDG.128 per tensor ----
    F12 uo, ud;
    if (fullQ) {
        const float4* __restrict__ O4 = (const float4*)origins;
        const float4* __restrict__ D4 = (const float4*)dirs;
        uo.v[0] = O4[f4]; uo.v[1] = O4[f4 + 1]; uo.v[2] = O4[f4 + 2];
        ud.v[0] = D4[f4]; ud.v[1] = D4[f4 + 1]; ud.v[2] = D4[f4 + 2];
    } else {  // tail thread: guarded scalar gather
        #pragma unroll
        for (int e = 0; e < 12; ++e) {
            const int f = ray0 * 3 + e;
            uo.f[e] = (f < n3) ? origins[f] : 0.0f;
            ud.f[e] = (f < n3) ? dirs[f]    : 0.0f;
        }
    }

    // ---- Ray classification (replaces the 64-iter march) ----
    // Unit d => sdf(t) = sqrt(t^2 + 2*hb*t + c0) - r, hb = (o-c).d, c0 = |o-c|^2.
    // Sphere tracing converges to t* = -hb - sqrt(disc), disc = hb^2 - c0 + r^2,
    // per-step contraction q = 1 - cos(alpha), cos(alpha) = sqrt(disc)/r.
    //  clear hit  (hb<0, disc > 0.04 r^2): ref s64 <= 0.8^63 ~ 8e-7 << eps and
    //     |t* - t64| <= 4e-6 -> identical mask & color.
    //  clear miss (hb>=0, or disc <= -2e-4): ref s64 > 1e-4 -> zeroed anyway.
    //  band (else, P ~ 4e-6/ray): exact 64-iteration reference recurrence.
    // p = o + t*d is computed HERE while o,d are live (no later reload).
    float hbv[RPT], c0v[RPT];
    bool  hit[RPT];
    bool  band_any = false;
    ull px2[RPT], py2[RPT], pz2[RPT];

    #pragma unroll
    for (int k = 0; k < RPT; ++k) {
        const float ox = uo.f[3 * k], oy = uo.f[3 * k + 1], oz = uo.f[3 * k + 2];
        const float dx = ud.f[3 * k], dy = ud.f[3 * k + 1], dz = ud.f[3 * k + 2];
        const float ux = ox - cx, uy = oy - cy, uz = oz - cz;
        const float c0 = fmaf(ux, ux, fmaf(uy, uy, uz * uz));
        const float hb = fmaf(ux, dx, fmaf(uy, dy, uz * dz));
        const float disc = fmaf(hb, hb, r2 - c0);
        const bool  toward = (hb < 0.0f);
        const bool  clear_hit = toward && (disc > 0.04f * r2);
        const bool  in_band = toward && !clear_hit && (disc > -2e-4f);
        band_any |= in_band;
        hit[k] = clear_hit;
        const float t = clear_hit ? (-hb - fsqrt_fast(disc)) : 0.0f;
        hbv[k] = hb;
        c0v[k] = c0;
        px2[k] = pack2(fmaf(t, dx, ox), fmaf(t, dx, ox));
        py2[k] = pack2(fmaf(t, dy, oy), fmaf(t, dy, oy));
        pz2[k] = pack2(fmaf(t, dz, oz), fmaf(t, dz, oz));
    }

    if (__any_sync(0xffffffffu, band_any)) {
        // Rare path (~5e-4 of warps): exact reference loop; o,d still live.
        #pragma unroll
        for (int k = 0; k < RPT; ++k) {
            const float b = 2.0f * hbv[k];
            float t = 0.0f, s = 0.0f;
            #pragma unroll 1
            for (int it = 0; it < MAX_ITERS; ++it) {
                s = sqrtf(fmaf(t, t + b, c0v[k])) - r;
                t += s;
            }
            hit[k] = (s < 1e-4f);
            const float px = fmaf(t, ud.f[3 * k],     uo.f[3 * k]);
            const float py = fmaf(t, ud.f[3 * k + 1], uo.f[3 * k + 1]);
            const float pz = fmaf(t, ud.f[3 * k + 2], uo.f[3 * k + 2]);
            px2[k] = pack2(px, px);
            py2[k] = pack2(py, py);
            pz2[k] = pack2(pz, pz);
        }
    }

    __syncthreads();   // shared weights ready

    // ---- MLP: h = relu(p@W1 + b1); col = sigmoid(h@W2 + b2) ----
    // Per pair: 4 broadcast LDS feed 24 FFMA2 (fma pipe) + 8 FMNMX (alu pipe).
    ull a0[RPT], a1[RPT], a2[RPT];
    #pragma unroll
    for (int k = 0; k < RPT; ++k) { a0[k] = 0ull; a1[k] = 0ull; a2[k] = 0ull; }

    const ulonglong2* __restrict__ Au = (const ulonglong2*)sA;
    const ulonglong2* __restrict__ Bu = (const ulonglong2*)sB;
    const ulonglong2* __restrict__ Cu = (const ulonglong2*)sC;
    const ull*        __restrict__ Du = (const ull*)sD;

    // Double-buffered weight loads: pair p+1's LDS issue before pair p's math.
    ulonglong2 wa = Au[0], wb = Bu[0], wc = Cu[0];
    ull        wd = Du[0];

    #pragma unroll 8
    for (int p = 0; p < NPAIR; ++p) {
        const int q = (p + 1) & (NPAIR - 1);
        const ulonglong2 na = Au[q];
        const ulonglong2 nb = Bu[q];
        const ulonglong2 nc = Cu[q];
        const ull        nd = Du[q];

        #pragma unroll
        for (int k = 0; k < RPT; ++k) {
            ull h = wb.y;
            h = ffma2(px2[k], wa.x, h);
            h = ffma2(py2[k], wa.y, h);
            h = ffma2(pz2[k], wb.x, h);
            float hl, hh;
            unpack2(h, hl, hh);
            hl = fmaxf(hl, 0.0f);      // relu on the alu pipe (in-place)
            hh = fmaxf(hh, 0.0f);
            h = pack2(hl, hh);
            a0[k] = ffma2(h, wc.x, a0[k]);
            a1[k] = ffma2(h, wc.y, a1[k]);
            a2[k] = ffma2(h, wd,   a2[k]);
        }

        wa = na; wb = nb; wc = nc; wd = nd;
    }

    // ---- Epilogue: sigmoid + vector store ----
    const float bb0 = b2[0], bb1 = b2[1], bb2 = b2[2];
    F12 uc;
    #pragma unroll
    for (int k = 0; k < RPT; ++k) {
        float l0, h0, l1, h1, l2, h2;
        unpack2(a0[k], l0, h0);
        unpack2(a1[k], l1, h1);
        unpack2(a2[k], l2, h2);
        const float z0 = bb0 + l0 + h0;
        const float z1 = bb1 + l1 + h1;
        const float z2 = bb2 + l2 + h2;
        const float c0 = __fdividef(1.0f, 1.0f + __expf(-z0));
        const float c1 = __fdividef(1.0f, 1.0f + __expf(-z1));
        const float c2 = __fdividef(1.0f, 1.0f + __expf(-z2));
        uc.f[3 * k]     = hit[k] ? c0 : 0.0f;
        uc.f[3 * k + 1] = hit[k] ? c1 : 0.0f;
        uc.f[3 * k + 2] = hit[k] ? c2 : 0.0f;
    }

    if (fullQ) {
        float4* __restrict__ OUT4 = (float4*)out;
        OUT4[f4]     = uc.v[0];
        OUT4[f4 + 1] = uc.v[1];
        OUT4[f4 + 2] = uc.v[2];
    } else {
        #pragma unroll
        for (int e = 0; e < 12; ++e) {
            const int f = ray0 * 3 + e;
            if (f < n3) out[f] = uc.f[e];
        }
    }
}

extern "C" void kernel_launch(void* const* d_in, const int* in_sizes, int n_in,
                              void* d_out, int out_size) {
    const float* origins = (const float*)d_in[0];
    const float* dirs    = (const float*)d_in[1];
    const float* center  = (const float*)d_in[2];
    const float* radius  = (const float*)d_in[3];
    const float* W1      = (const float*)d_in[4];
    const float* b1      = (const float*)d_in[5];
    const float* W2      = (const float*)d_in[6];
    const float* b2      = (const float*)d_in[7];
    float* out = (float*)d_out;

    const int n = in_sizes[0] / 3;
    const int per_block = TPB * RPT;
    const int blocks = (n + per_block - 1) / per_block;
    sphere_trace_mlp_kernel<<<blocks, TPB>>>(origins, dirs, center, radius,
                                             W1, b1, W2, b2, out, n);
}